// round 13
// baseline (speedup 1.0000x reference)
#include <cuda_runtime.h>
#include <cstdint>

// Problem constants (fixed shapes in reference_code)
#define BB     1024
#define CC     20
#define NN     26
#define VDIM   128
#define NSPL   10
#define NWORDS 100000

#define GATHER_BLOCKS 3328                 // ceil(BB*NN / 8 warps)
#define COPY_BLOCKS   640                  // fused SM-copy blocks
#define PREFIX_ELEMS  10000000ll           // 40 MB of D copied by SM during phase2
#define PREFIX_F4     (PREFIX_ELEMS / 4)   // 2,500,000 float4 (exact)

// K1: x[b,v] = (1/C) * sum_c ( D[knot[b], ctx[b,c], v] * x_vals[b] + W[ctx[b,c], v] )
// One block per b, 128 threads (v = tid). Writes x to scratch.
__global__ void __launch_bounds__(128)
dmspline_phase1(const float* __restrict__ x_vals,
                const int*   __restrict__ knot_ids,
                const int*   __restrict__ context_ids,
                const float* __restrict__ D,
                const float* __restrict__ W,
                float* __restrict__ xscratch)
{
    __shared__ int sctx[CC];
    const int bid = blockIdx.x;
    const int tid = threadIdx.x;

    if (tid < CC) sctx[tid] = context_ids[bid * CC + tid];
    __syncthreads();

    const int   knot = knot_ids[bid];
    const float xv   = x_vals[bid];
    const float* __restrict__ Dk = D + (size_t)knot * NWORDS * VDIM;

    float acc = 0.0f;
    #pragma unroll
    for (int c = 0; c < CC; ++c) {
        const int ctx = sctx[c];
        const float d = __ldg(Dk + (size_t)ctx * VDIM + tid);
        const float w = __ldg(W  + (size_t)ctx * VDIM + tid);
        acc = fmaf(d, xv, acc) + w;
    }
    xscratch[bid * VDIM + tid] = acc * (1.0f / CC);
}

// K2 (fused): blocks [0, GATHER_BLOCKS) compute scores (one warp per (b,n));
// blocks [GATHER_BLOCKS, +COPY_BLOCKS) stream-copy the first PREFIX_ELEMS of
// D into the output, using the DRAM/LTS bandwidth the replay-bound gather
// leaves idle. The two groups touch disjoint memory.
__global__ void __launch_bounds__(256)
dmspline_phase2(const int*   __restrict__ target_ids,
                const float* __restrict__ O,
                const float* __restrict__ xscratch,
                const float* __restrict__ D,
                float* __restrict__ out,
                int do_copy)
{
    if (blockIdx.x < GATHER_BLOCKS) {
        const int gw   = blockIdx.x * 8 + (threadIdx.x >> 5);  // global warp id
        const int lane = threadIdx.x & 31;
        if (gw >= BB * NN) return;

        const int b = gw / NN;
        const int n = gw - b * NN;

        const int id = __ldg(target_ids + b * NN + n);
        const float* __restrict__ Ocol = O + id;
        const float* __restrict__ xrow = xscratch + b * VDIM;

        // Front-load all 4 gathers + 4 coalesced x loads.
        float o0 = __ldg(Ocol + (size_t)(lane      ) * NWORDS);
        float o1 = __ldg(Ocol + (size_t)(lane + 32 ) * NWORDS);
        float o2 = __ldg(Ocol + (size_t)(lane + 64 ) * NWORDS);
        float o3 = __ldg(Ocol + (size_t)(lane + 96 ) * NWORDS);
        float x0 = __ldg(xrow + lane);
        float x1 = __ldg(xrow + lane + 32);
        float x2 = __ldg(xrow + lane + 64);
        float x3 = __ldg(xrow + lane + 96);

        float s = 0.0f;
        s = fmaf(x0, o0, s);
        s = fmaf(x1, o1, s);
        s = fmaf(x2, o2, s);
        s = fmaf(x3, o3, s);

        #pragma unroll
        for (int off = 16; off; off >>= 1)
            s += __shfl_down_sync(0xffffffffu, s, off);
        if (lane == 0) out[b * NN + n] = s;
    } else if (do_copy) {
        // SM copy of D[0 : PREFIX_ELEMS) -> out D-region prefix (streaming).
        const float4* __restrict__ src = (const float4*)D;
        float4*       __restrict__ dst = (float4*)(out + BB * NN);
        const size_t cb     = blockIdx.x - GATHER_BLOCKS;
        const size_t stride = (size_t)COPY_BLOCKS * 256;
        for (size_t i = cb * 256 + threadIdx.x; i < (size_t)PREFIX_F4; i += stride) {
            float4 v = __ldcs(src + i);
            __stcs(dst + i, v);
        }
    }
}

extern "C" void kernel_launch(void* const* d_in, const int* in_sizes, int n_in,
                              void* d_out, int out_size)
{
    const float* x_vals      = (const float*)d_in[0];
    const int*   knot_ids    = (const int*)  d_in[1];
    const int*   context_ids = (const int*)  d_in[2];
    const int*   target_ids  = (const int*)  d_in[3];
    const float* D           = (const float*)d_in[4];
    const float* W           = (const float*)d_in[5];
    const float* O           = (const float*)d_in[6];
    float*       out         = (float*)d_out;

    const long long dElems = (long long)NSPL * NWORDS * VDIM;   // 128,000,000
    const long long need   = (long long)BB * NN + dElems;
    const bool full_out = ((long long)out_size >= need);

    float* dstD = out + (size_t)BB * NN;

    // x scratch lives in the TAIL of the D-output region: written by phase1,
    // read by phase2, then overwritten with correct D data by the trailing
    // memcpy (same stream -> exact ordering). Disjoint from the SM-copied
    // prefix [0, PREFIX_ELEMS).
    float* xscratch = dstD + (size_t)(dElems - (long long)BB * VDIM);

    // Phase 1: x into scratch (~3 us)
    dmspline_phase1<<<BB, 128>>>(x_vals, knot_ids, context_ids, D, W, xscratch);

    // Phase 2 (fused gather + prefix copy): ~24-27 us
    dmspline_phase2<<<GATHER_BLOCKS + COPY_BLOCKS, 256>>>(
        target_ids, O, xscratch, D, out, full_out ? 1 : 0);

    // Remainder of D via the driver's D2D memcpy (7.2 TB/s; serial with
    // kernels — proven). Covers [PREFIX_ELEMS, dElems), including the
    // scratch tail.
    if (full_out) {
        cudaMemcpyAsync(dstD + PREFIX_ELEMS, D + PREFIX_ELEMS,
                        (size_t)(dElems - PREFIX_ELEMS) * sizeof(float),
                        cudaMemcpyDeviceToDevice, 0);
    }
}

// round 15
// speedup vs baseline: 1.8835x; 1.8835x over previous
#include <cuda_runtime.h>
#include <cstdint>

// Problem constants (fixed shapes in reference_code)
#define BB     1024
#define CC     20
#define NN     26
#define VDIM   128
#define NSPL   10
#define NWORDS 100000

#define GATHER_BLOCKS 3328                  // ceil(BB*NN / 8 warps)
#define COPY_BLOCKS   448                   // fused SM-copy blocks (milder contention)
// 40 MiB prefix: 10,485,760 floats = 41,943,040 bytes (multiple of 4096).
// dst offset = 106,496 + 41,943,040 bytes -> also 4KiB-aligned.
// Keeps BOTH endpoints of the trailing driver memcpy on the 4KiB-aligned
// fast path (R13 proved misaligned D2D drops 7.2 -> ~3.0 TB/s).
#define PREFIX_ELEMS  10485760ll
#define PREFIX_F4     (PREFIX_ELEMS / 4)    // 2,621,440 float4 (exact)

// K1: x[b,v] = (1/C) * sum_c ( D[knot[b], ctx[b,c], v] * x_vals[b] + W[ctx[b,c], v] )
// One block per b, 128 threads (v = tid). Writes x to scratch.
__global__ void __launch_bounds__(128)
dmspline_phase1(const float* __restrict__ x_vals,
                const int*   __restrict__ knot_ids,
                const int*   __restrict__ context_ids,
                const float* __restrict__ D,
                const float* __restrict__ W,
                float* __restrict__ xscratch)
{
    __shared__ int sctx[CC];
    const int bid = blockIdx.x;
    const int tid = threadIdx.x;

    if (tid < CC) sctx[tid] = context_ids[bid * CC + tid];
    __syncthreads();

    const int   knot = knot_ids[bid];
    const float xv   = x_vals[bid];
    const float* __restrict__ Dk = D + (size_t)knot * NWORDS * VDIM;

    float acc = 0.0f;
    #pragma unroll
    for (int c = 0; c < CC; ++c) {
        const int ctx = sctx[c];
        const float d = __ldg(Dk + (size_t)ctx * VDIM + tid);
        const float w = __ldg(W  + (size_t)ctx * VDIM + tid);
        acc = fmaf(d, xv, acc) + w;
    }
    xscratch[bid * VDIM + tid] = acc * (1.0f / CC);
}

// K2 (fused): blocks [0, GATHER_BLOCKS) compute scores (one warp per (b,n));
// blocks [GATHER_BLOCKS, +COPY_BLOCKS) stream-copy the first PREFIX_ELEMS of
// D into the output, using DRAM bandwidth the replay-bound gather leaves idle.
__global__ void __launch_bounds__(256)
dmspline_phase2(const int*   __restrict__ target_ids,
                const float* __restrict__ O,
                const float* __restrict__ xscratch,
                const float* __restrict__ D,
                float* __restrict__ out,
                int do_copy)
{
    if (blockIdx.x < GATHER_BLOCKS) {
        const int gw   = blockIdx.x * 8 + (threadIdx.x >> 5);  // global warp id
        const int lane = threadIdx.x & 31;
        if (gw >= BB * NN) return;

        const int b = gw / NN;
        const int n = gw - b * NN;

        const int id = __ldg(target_ids + b * NN + n);
        const float* __restrict__ Ocol = O + id;
        const float* __restrict__ xrow = xscratch + b * VDIM;

        // Front-load all 4 gathers + 4 coalesced x loads.
        float o0 = __ldg(Ocol + (size_t)(lane      ) * NWORDS);
        float o1 = __ldg(Ocol + (size_t)(lane + 32 ) * NWORDS);
        float o2 = __ldg(Ocol + (size_t)(lane + 64 ) * NWORDS);
        float o3 = __ldg(Ocol + (size_t)(lane + 96 ) * NWORDS);
        float x0 = __ldg(xrow + lane);
        float x1 = __ldg(xrow + lane + 32);
        float x2 = __ldg(xrow + lane + 64);
        float x3 = __ldg(xrow + lane + 96);

        float s = 0.0f;
        s = fmaf(x0, o0, s);
        s = fmaf(x1, o1, s);
        s = fmaf(x2, o2, s);
        s = fmaf(x3, o3, s);

        #pragma unroll
        for (int off = 16; off; off >>= 1)
            s += __shfl_down_sync(0xffffffffu, s, off);
        if (lane == 0) out[b * NN + n] = s;
    } else if (do_copy) {
        // SM copy of D[0 : PREFIX_ELEMS) -> out D-region prefix (streaming).
        const float4* __restrict__ src = (const float4*)D;
        float4*       __restrict__ dst = (float4*)(out + BB * NN);
        const size_t cb     = blockIdx.x - GATHER_BLOCKS;
        const size_t stride = (size_t)COPY_BLOCKS * 256;
        for (size_t i = cb * 256 + threadIdx.x; i < (size_t)PREFIX_F4; i += stride) {
            float4 v = __ldcs(src + i);
            __stcs(dst + i, v);
        }
    }
}

extern "C" void kernel_launch(void* const* d_in, const int* in_sizes, int n_in,
                              void* d_out, int out_size)
{
    const float* x_vals      = (const float*)d_in[0];
    const int*   knot_ids    = (const int*)  d_in[1];
    const int*   context_ids = (const int*)  d_in[2];
    const int*   target_ids  = (const int*)  d_in[3];
    const float* D           = (const float*)d_in[4];
    const float* W           = (const float*)d_in[5];
    const float* O           = (const float*)d_in[6];
    float*       out         = (float*)d_out;

    const long long dElems = (long long)NSPL * NWORDS * VDIM;   // 128,000,000
    const long long need   = (long long)BB * NN + dElems;
    const bool full_out = ((long long)out_size >= need);

    float* dstD = out + (size_t)BB * NN;

    // x scratch lives in the TAIL of the D-output region: written by phase1,
    // read by phase2, then overwritten with correct D data by the trailing
    // memcpy (same-stream ordering). Disjoint from the SM-copied prefix.
    float* xscratch = dstD + (size_t)(dElems - (long long)BB * VDIM);

    // Phase 1: x into scratch (~3 us)
    dmspline_phase1<<<BB, 128>>>(x_vals, knot_ids, context_ids, D, W, xscratch);

    // Phase 2 (fused gather + 40 MiB prefix copy): ~27-29 us
    dmspline_phase2<<<GATHER_BLOCKS + COPY_BLOCKS, 256>>>(
        target_ids, O, xscratch, D, out, full_out ? 1 : 0);

    // Remainder of D via the driver's D2D memcpy. BOTH endpoints 4KiB-aligned
    // -> fast path (~7.2 TB/s). Covers [PREFIX_ELEMS, dElems) incl. scratch.
    if (full_out) {
        cudaMemcpyAsync(dstD + PREFIX_ELEMS, D + PREFIX_ELEMS,
                        (size_t)(dElems - PREFIX_ELEMS) * sizeof(float),
                        cudaMemcpyDeviceToDevice, 0);
    }
}

// round 16
// speedup vs baseline: 1.8894x; 1.0031x over previous
#include <cuda_runtime.h>
#include <cstdint>

// Problem constants (fixed shapes in reference_code)
#define BB     1024
#define CC     20
#define NN     26
#define VDIM   128
#define NSPL   10
#define NWORDS 100000

// K1: x[b,v] = (1/C) * sum_c ( D[knot[b], ctx[b,c], v] * x_vals[b] + W[ctx[b,c], v] )
// One block per b, 128 threads (v = tid). Writes x to scratch (tail of d_out).
__global__ void __launch_bounds__(128)
dmspline_phase1(const float* __restrict__ x_vals,
                const int*   __restrict__ knot_ids,
                const int*   __restrict__ context_ids,
                const float* __restrict__ D,
                const float* __restrict__ W,
                float* __restrict__ xscratch)
{
    __shared__ int sctx[CC];
    const int bid = blockIdx.x;
    const int tid = threadIdx.x;

    if (tid < CC) sctx[tid] = context_ids[bid * CC + tid];
    __syncthreads();

    const int   knot = knot_ids[bid];
    const float xv   = x_vals[bid];
    const float* __restrict__ Dk = D + (size_t)knot * NWORDS * VDIM;

    float acc = 0.0f;
    #pragma unroll
    for (int c = 0; c < CC; ++c) {
        const int ctx = sctx[c];
        const float d = __ldg(Dk + (size_t)ctx * VDIM + tid);
        const float w = __ldg(W  + (size_t)ctx * VDIM + tid);
        acc = fmaf(d, xv, acc) + w;
    }
    xscratch[bid * VDIM + tid] = acc * (1.0f / CC);
}

// K2: scores[b,n] = sum_v x[b,v] * O[v, tgt[b,n]]
// ONE OUTPUT PER 128-THREAD GROUP (4 warps), TWO OUTPUTS PER BLOCK.
// Each thread does exactly ONE scattered O load -> each warp contributes one
// 32-line LDG. 4x more distinct LDGs in flight per SM than the 4-loads-per-
// warp version, letting the L1tex queue run at the cross-LDG wavefront rate
// (1.0 cyc/wf) instead of the within-LDG replay rate (2.07 cyc/wf).
// BB*NN = 26624 outputs -> 13312 blocks exactly (no remainder).
__global__ void __launch_bounds__(256)
dmspline_phase2(const int*   __restrict__ target_ids,
                const float* __restrict__ O,
                const float* __restrict__ xscratch,
                float* __restrict__ out)
{
    __shared__ float part[8];   // 2 groups x 4 warp-partials

    const int group = threadIdx.x >> 7;        // 0..1
    const int gt    = threadIdx.x & 127;       // v index 0..127
    const int gout  = blockIdx.x * 2 + group;  // global output id (always < 26624)

    const int b = gout / NN;

    const int id = __ldg(target_ids + gout);   // broadcast within group
    const float o = __ldg(O + (size_t)gt * NWORDS + id);   // 1 scattered load
    const float x = __ldg(xscratch + b * VDIM + gt);       // coalesced

    float s = x * o;
    #pragma unroll
    for (int off = 16; off; off >>= 1)
        s += __shfl_down_sync(0xffffffffu, s, off);

    const int lane = threadIdx.x & 31;
    const int wig  = (threadIdx.x >> 5) & 3;   // warp index within group
    if (lane == 0) part[group * 4 + wig] = s;
    __syncthreads();

    if (gt == 0) {
        out[gout] = (part[group * 4 + 0] + part[group * 4 + 1])
                  + (part[group * 4 + 2] + part[group * 4 + 3]);
    }
}

extern "C" void kernel_launch(void* const* d_in, const int* in_sizes, int n_in,
                              void* d_out, int out_size)
{
    const float* x_vals      = (const float*)d_in[0];
    const int*   knot_ids    = (const int*)  d_in[1];
    const int*   context_ids = (const int*)  d_in[2];
    const int*   target_ids  = (const int*)  d_in[3];
    const float* D           = (const float*)d_in[4];
    const float* W           = (const float*)d_in[5];
    const float* O           = (const float*)d_in[6];
    float*       out         = (float*)d_out;

    const long long dElems = (long long)NSPL * NWORDS * VDIM;   // 128,000,000
    const long long need   = (long long)BB * NN + dElems;
    const bool full_out = ((long long)out_size >= need);

    float* dstD = out + (size_t)BB * NN;

    // x scratch in the TAIL of the D-output region: written by phase1, read
    // by phase2, then overwritten with correct D data by the memcpy below
    // (same-stream ordering). BB*VDIM = 131072 floats << dElems.
    float* xscratch = dstD + (size_t)(dElems - (long long)BB * VDIM);

    // Phase 1: x into scratch (~3 us)
    dmspline_phase1<<<BB, 128>>>(x_vals, knot_ids, context_ids, D, W, xscratch);

    // Phase 2: one output per 4-warp group; 13312 blocks (~13-16 us target)
    dmspline_phase2<<<(BB * NN) / 2, 256>>>(target_ids, O, xscratch, out);

    // Full D pass-through via the driver's D2D memcpy. Offsets 0 / 106,496 B
    // (4KiB-multiple) -> aligned fast path (~7.2 TB/s, proven R5).
    if (full_out) {
        cudaMemcpyAsync(dstD, D, (size_t)dElems * sizeof(float),
                        cudaMemcpyDeviceToDevice, 0);
    }
}

// round 17
// speedup vs baseline: 1.9306x; 1.0218x over previous
#include <cuda_runtime.h>
#include <cstdint>

// Problem constants (fixed shapes in reference_code)
#define BB     1024
#define CC     20
#define NN     26
#define VDIM   128
#define NSPL   10
#define NWORDS 100000

// Monolithic scores kernel, TWO BLOCKS PER BATCH ROW (2048 blocks).
// Each block: phase1 computes x[b,:] into smem (the twin block's D/W reads
// are L2 hits), phase2 handles 13 of the 26 outputs with front-loaded
// scattered gathers (up to 8 loads in flight per thread).
__global__ void __launch_bounds__(256)
dmspline_scores(const float* __restrict__ x_vals,
                const int*   __restrict__ knot_ids,
                const int*   __restrict__ context_ids,
                const int*   __restrict__ target_ids,
                const float* __restrict__ D,
                const float* __restrict__ W,
                const float* __restrict__ O,
                float* __restrict__ out)
{
    __shared__ float sx[VDIM];
    __shared__ int   sctx[CC];

    const int b    = blockIdx.x >> 1;
    const int half = blockIdx.x & 1;       // 0 -> n in [0,13), 1 -> [13,26)
    const int tid  = threadIdx.x;

    // ---- stage context ids through shared ----
    if (tid < CC) sctx[tid] = context_ids[b * CC + tid];
    __syncthreads();

    // ---- phase 1: x[v] for v = tid (threads 0..127) ----
    if (tid < VDIM) {
        const int   knot = knot_ids[b];
        const float xv   = x_vals[b];
        const float* __restrict__ Dk = D + (size_t)knot * NWORDS * VDIM;
        float acc = 0.0f;
        #pragma unroll
        for (int c = 0; c < CC; ++c) {
            const int ctx = sctx[c];
            const float d = __ldg(Dk + (size_t)ctx * VDIM + tid);
            const float w = __ldg(W  + (size_t)ctx * VDIM + tid);
            acc = fmaf(d, xv, acc) + w;
        }
        sx[tid] = acc * (1.0f / CC);
    }
    __syncthreads();

    // ---- phase 2: 13 outputs over 8 warps; warp w takes n_local = w, w+8.
    // All scattered O loads for both outputs are front-loaded (<=8 in flight).
    const int warp = tid >> 5;
    const int lane = tid & 31;
    const int nbase = half * 13;

    int nloc[2];
    int cnt = 0;
    #pragma unroll
    for (int nl = warp; nl < 13; nl += 8) nloc[cnt++] = nl;

    const float* __restrict__ ocol[2];
    #pragma unroll
    for (int i = 0; i < 2; ++i) {
        if (i < cnt) ocol[i] = O + __ldg(target_ids + b * NN + nbase + nloc[i]);
    }

    float ov[2][4];
    #pragma unroll
    for (int i = 0; i < 2; ++i) {
        if (i < cnt) {
            #pragma unroll
            for (int k = 0; k < 4; ++k) {
                ov[i][k] = __ldg(ocol[i] + (size_t)(lane + 32 * k) * NWORDS);
            }
        }
    }

    float xs[4];
    #pragma unroll
    for (int k = 0; k < 4; ++k) xs[k] = sx[lane + 32 * k];

    #pragma unroll
    for (int i = 0; i < 2; ++i) {
        if (i < cnt) {
            float s = 0.0f;
            #pragma unroll
            for (int k = 0; k < 4; ++k) s = fmaf(xs[k], ov[i][k], s);
            #pragma unroll
            for (int off = 16; off; off >>= 1)
                s += __shfl_down_sync(0xffffffffu, s, off);
            if (lane == 0) out[b * NN + nbase + nloc[i]] = s;
        }
    }
}

extern "C" void kernel_launch(void* const* d_in, const int* in_sizes, int n_in,
                              void* d_out, int out_size)
{
    const float* x_vals      = (const float*)d_in[0];
    const int*   knot_ids    = (const int*)  d_in[1];
    const int*   context_ids = (const int*)  d_in[2];
    const int*   target_ids  = (const int*)  d_in[3];
    const float* D           = (const float*)d_in[4];
    const float* W           = (const float*)d_in[5];
    const float* O           = (const float*)d_in[6];
    float*       out         = (float*)d_out;

    // Scores: one kernel, 2048 blocks (2 per batch row).
    dmspline_scores<<<2 * BB, 256>>>(x_vals, knot_ids, context_ids, target_ids,
                                     D, W, O, out);

    // Full D pass-through via the driver's D2D memcpy. Offsets 0 / 106,496 B
    // (both 4KiB-aligned) -> fast path (~7.2 TB/s, proven R5/R12).
    const long long dElems = (long long)NSPL * NWORDS * VDIM;
    const long long need   = (long long)BB * NN + dElems;
    if ((long long)out_size >= need) {
        cudaMemcpyAsync(out + (size_t)BB * NN, D,
                        (size_t)dElems * sizeof(float),
                        cudaMemcpyDeviceToDevice, 0);
    }
}